// round 11
// baseline (speedup 1.0000x reference)
#include <cuda_runtime.h>
#include <cuda_fp16.h>
#include <cstdint>

// out[b,i,j,o] = bias[o] + sum_{th,tw,c} x[b, i-1-th, j-1-tw, c] * K[o,c,th,tw]
// fp16 m16n8k16 mma.sync implicit GEMM (fp32 accum), all 9 tap weight slices smem-resident
// (XOR-swizzled 128B rows). 512-thread CTA with intra-CTA split-K (2 warp-groups of 8),
// partial reduction through smem. 2 CTAs/SM -> 32 warps/SM.

#define BATCH 8
#define HH 64
#define WW 64
#define CIN 64
#define FF 64

#define SROWSH 67                         // s = input col + 3 (0..66)
#define XS_BYTES (4 * SROWSH * 128)
#define WS_BYTE_OFF XS_BYTES
#define BIAS_BYTE_OFF (XS_BYTES + 9 * FF * 128)
#define SMEM_BYTES (BIAS_BYTE_OFF + 64 * 4)       // 108288 B -> 2 CTAs/SM

__device__ __forceinline__ uint32_t smem_u32(const void* p) {
    uint32_t a;
    asm("{ .reg .u64 t; cvta.to.shared.u64 t, %1; cvt.u32.u64 %0, t; }" : "=r"(a) : "l"(p));
    return a;
}
__device__ __forceinline__ void ldsm4(uint32_t* r, uint32_t addr) {
    asm volatile("ldmatrix.sync.aligned.m8n8.x4.shared.b16 {%0,%1,%2,%3}, [%4];"
                 : "=r"(r[0]), "=r"(r[1]), "=r"(r[2]), "=r"(r[3]) : "r"(addr));
}
__device__ __forceinline__ void mma16(float* d, const uint32_t* a, uint32_t b0, uint32_t b1) {
    asm volatile("mma.sync.aligned.m16n8k16.row.col.f32.f16.f16.f32 "
                 "{%0,%1,%2,%3}, {%4,%5,%6,%7}, {%8,%9}, {%0,%1,%2,%3};"
                 : "+f"(d[0]), "+f"(d[1]), "+f"(d[2]), "+f"(d[3])
                 : "r"(a[0]), "r"(a[1]), "r"(a[2]), "r"(a[3]), "r"(b0), "r"(b1));
}
__device__ __forceinline__ void cp16(uint32_t dst, const void* src) {
    asm volatile("cp.async.cg.shared.global [%0], [%1], 16;"
                 :: "r"(dst), "l"(__cvta_generic_to_global(src)) : "memory");
}
#define CP_COMMIT() asm volatile("cp.async.commit_group;" ::: "memory")
#define CP_WAIT0()  asm volatile("cp.async.wait_group 0;" ::: "memory")

// Repacked fp16 weights: [tap][f][c], tap = th*3+tw  (8KB per tap, contiguous)
__device__ __half g_w3[9 * FF * CIN];

__global__ void wre3_kernel(const float* __restrict__ kin) {
    int idx = blockIdx.x * blockDim.x + threadIdx.x;
    if (idx >= 9 * FF * CIN) return;
    int c   = idx & 63;
    int f   = (idx >> 6) & 63;
    int tap = idx >> 12;
    int th = tap / 3, tw = tap % 3;
    g_w3[idx] = __float2half_rn(kin[((f * CIN + c) * 3 + th) * 3 + tw]);
}

// 18 rounds starting at compile-time BASE (it = BASE+rr; tap = it>>2, ks = it&3)
template <int BASE>
__device__ __forceinline__ void run_half(uint32_t sb, uint32_t sb_ws,
                                         int r, int jb, int mA, int kcA,
                                         uint32_t rbB0, uint32_t rbB1, int sB, int kcB,
                                         float (&acc)[2][4][4]) {
    #pragma unroll
    for (int rr = 0; rr < 18; ++rr) {
        const int it = BASE + rr;
        const int tap = it >> 2, ks = it & 3;
        const int th = tap / 3, tw = tap - 3 * th;
        const int rowA0 = (r + 2 - th) * SROWSH + (jb + 2 - tw) + mA;
        const uint32_t rbA0 = sb + (uint32_t)(rowA0 * 128);
        const int sA = rowA0 & 7;
        const uint32_t wt = (uint32_t)(tap * 8192);
        const int ca = 2 * ks + kcA;
        const int cb = 2 * ks + kcB;

        uint32_t a0[4], a1[4], b0[4], b1[4];
        ldsm4(a0, rbA0 + ((ca ^ sA) << 4));
        ldsm4(a1, rbA0 + 16 * 128 + ((ca ^ sA) << 4));
        ldsm4(b0, rbB0 + wt + ((cb ^ sB) << 4));
        ldsm4(b1, rbB1 + wt + ((cb ^ sB) << 4));

        mma16(acc[0][0], a0, b0[0], b0[2]); mma16(acc[1][0], a1, b0[0], b0[2]);
        mma16(acc[0][1], a0, b0[1], b0[3]); mma16(acc[1][1], a1, b0[1], b0[3]);
        mma16(acc[0][2], a0, b1[0], b1[2]); mma16(acc[1][2], a1, b1[0], b1[2]);
        mma16(acc[0][3], a0, b1[1], b1[3]); mma16(acc[1][3], a1, b1[1], b1[3]);
    }
}

__global__ __launch_bounds__(512, 2)
void conv_mma(const float* __restrict__ x,
              const float* __restrict__ bias,
              float* __restrict__ out) {
    extern __shared__ char smc[];
    const uint32_t sb    = smem_u32(smc);
    const uint32_t sb_ws = sb + WS_BYTE_OFF;
    float* sbias = (float*)(smc + BIAS_BYTE_OFF);

    const int tid = threadIdx.x;
    const int b  = blockIdx.x >> 5;
    const int i0 = (blockIdx.x & 31) * 2;       // 2 output rows per CTA

    // ---- all 9 weight tap slices via cp.async (4608 x 16B chunks, XOR-swizzled) ----
    #pragma unroll
    for (int k = 0; k < 9; ++k) {
        int ch = tid + 512 * k;                 // 0..4607
        int fr = ch >> 3;                       // tap*64 + f
        int k8 = ch & 7;
        cp16(sb_ws + (uint32_t)(fr * 128 + ((k8 ^ (fr & 7)) << 4)),
             g_w3 + fr * 64 + k8 * 8);
    }
    CP_COMMIT();

    // ---- zero padding rows ----
    {
        uint4 z = make_uint4(0u, 0u, 0u, 0u);
        if (tid < 96) {
            int t = tid / 24, q = tid % 24;
            *(uint4*)(smc + t * (SROWSH * 128) + q * 16) = z;
        }
        int nneg = (i0 == 0) ? 3 : (i0 == 2 ? 1 : 0);
        if (nneg) {
            uint4* p = (uint4*)smc;
            for (int k = tid; k < nneg * SROWSH * 8; k += 512) p[k] = z;
        }
    }

    // ---- stage 4 input rows (i0-3 .. i0) pixel-major fp16, swizzled (2 planes per thread-half) ----
    {
        const int t2  = tid & 255;
        const int tpar = tid >> 8;              // 0: planes 0-1, 1: planes 2-3
        const int c4 = t2 & 15;
        const int jh = t2 >> 4;
        const int sub = (c4 & 1) * 8;
        #pragma unroll
        for (int tt = 0; tt < 2; ++tt) {
            int t = 2 * tpar + tt;
            int row = i0 - 3 + t;
            if (row < 0) continue;
            const float4* src = (const float4*)(x + ((size_t)(b * HH + row) * WW) * CIN);
            #pragma unroll
            for (int jj = 0; jj < 4; ++jj) {
                int j = jj * 16 + jh;
                float4 v = src[j * (CIN / 4) + c4];
                __half2 h0 = __float22half2_rn(make_float2(v.x, v.y));
                __half2 h1 = __float22half2_rn(make_float2(v.z, v.w));
                uint2 w;
                w.x = *(uint32_t*)&h0;
                w.y = *(uint32_t*)&h1;
                int rowid = t * SROWSH + j + 3;
                *(uint2*)(smc + rowid * 128 + (((c4 >> 1) ^ (rowid & 7)) << 4) + sub) = w;
            }
        }
        if (tid < 64) sbias[tid] = bias[tid];
    }

    CP_WAIT0();
    __syncthreads();

    // ---- 16 warps: (wm 0..3) x (wn 0..1) x (kc 0..1 split-K) ----
    const int lane = tid & 31, w = tid >> 5;
    const int lq = lane >> 2, lr = lane & 3;
    const int wm = w & 3;
    const int wn = (w >> 2) & 1;
    const int kc = w >> 3;
    const int n0 = wn * 32;
    const int r  = wm >> 1;
    const int jb = (wm & 1) * 32;

    const int mA  = lane & 15;
    const int kcA = lane >> 4;
    const int fB  = (lane & 7) + 8 * ((lane >> 3) & 1);
    const int kcB = lane >> 4;

    const uint32_t rbB0 = sb_ws + (uint32_t)((n0 + fB) * 128);
    const uint32_t rbB1 = rbB0 + 16 * 128;
    const int sB = fB & 7;

    float acc[2][4][4];
    #pragma unroll
    for (int mt = 0; mt < 2; ++mt)
        #pragma unroll
        for (int nt = 0; nt < 4; ++nt)
            #pragma unroll
            for (int q = 0; q < 4; ++q) acc[mt][nt][q] = 0.0f;

    if (kc == 0) run_half<0 >(sb, sb_ws, r, jb, mA, kcA, rbB0, rbB1, sB, kcB, acc);
    else         run_half<18>(sb, sb_ws, r, jb, mA, kcA, rbB0, rbB1, sB, kcB, acc);

    // ---- split-K reduction through (now dead) weight smem region ----
    __syncthreads();                            // all MMAs done; weights dead
    const uint32_t pbase = sb_ws + (uint32_t)((w & 7) * 4096) + (uint32_t)(lane * 16);
    if (kc == 1) {
        #pragma unroll
        for (int mt = 0; mt < 2; ++mt)
            #pragma unroll
            for (int nt = 0; nt < 4; ++nt) {
                float4 v = make_float4(acc[mt][nt][0], acc[mt][nt][1],
                                       acc[mt][nt][2], acc[mt][nt][3]);
                asm volatile("st.shared.v4.f32 [%0], {%1,%2,%3,%4};"
                             :: "r"(pbase + (uint32_t)((mt * 4 + nt) * 512)),
                                "f"(v.x), "f"(v.y), "f"(v.z), "f"(v.w) : "memory");
            }
    }
    __syncthreads();

    if (kc == 0) {
        // add partner partials, bias, store
        const int i = i0 + r;
        #pragma unroll
        for (int mt = 0; mt < 2; ++mt) {
            int j = jb + mt * 16 + lq;
            float* o0 = out + (((size_t)(b * HH + i) * WW + j) * FF);
            float* o1 = o0 + 8 * FF;            // pixel +8
            #pragma unroll
            for (int nt = 0; nt < 4; ++nt) {
                float4 p;
                asm volatile("ld.shared.v4.f32 {%0,%1,%2,%3}, [%4];"
                             : "=f"(p.x), "=f"(p.y), "=f"(p.z), "=f"(p.w)
                             : "r"(pbase + (uint32_t)((mt * 4 + nt) * 512)));
                int f = n0 + nt * 8 + 2 * lr;
                float2 v0 = make_float2(acc[mt][nt][0] + p.x + sbias[f],
                                        acc[mt][nt][1] + p.y + sbias[f + 1]);
                float2 v1 = make_float2(acc[mt][nt][2] + p.z + sbias[f],
                                        acc[mt][nt][3] + p.w + sbias[f + 1]);
                *(float2*)(o0 + f) = v0;
                *(float2*)(o1 + f) = v1;
            }
        }
    }
}

extern "C" void kernel_launch(void* const* d_in, const int* in_sizes, int n_in,
                              void* d_out, int out_size) {
    const float* x    = (const float*)d_in[0];
    const float* kern = (const float*)d_in[1];
    const float* bias = (const float*)d_in[2];
    float* out = (float*)d_out;

    cudaFuncSetAttribute(conv_mma, cudaFuncAttributeMaxDynamicSharedMemorySize, SMEM_BYTES);

    wre3_kernel<<<(9 * FF * CIN + 255) / 256, 256>>>(kern);
    conv_mma<<<BATCH * 32, 512, SMEM_BYTES>>>(x, bias, out);
}

// round 12
// speedup vs baseline: 1.0772x; 1.0772x over previous
#include <cuda_runtime.h>
#include <cuda_fp16.h>
#include <cstdint>

// out[b,i,j,o] = bias[o] + sum_{th,tw,c} x[b, i-1-th, j-1-tw, c] * K[o,c,th,tw]
// fp16 m16n8k16 mma.sync implicit GEMM (fp32 accum). All 9 tap weight slices smem-resident
// (XOR-swizzled 128B rows). Two-phase weight arrival: mainloop starts after taps 0-4 land;
// taps 5-8 stream in under the first 20 rounds.

#define BATCH 8
#define HH 64
#define WW 64
#define CIN 64
#define FF 64

#define SROWSH 67                         // s = input col + 3 (0..66)
#define XS_BYTES (4 * SROWSH * 128)
#define WS_BYTE_OFF XS_BYTES
#define BIAS_BYTE_OFF (XS_BYTES + 9 * FF * 128)
#define SMEM_BYTES (BIAS_BYTE_OFF + 64 * 4)       // 108288 B -> 2 CTAs/SM

__device__ __forceinline__ uint32_t smem_u32(const void* p) {
    uint32_t a;
    asm("{ .reg .u64 t; cvta.to.shared.u64 t, %1; cvt.u32.u64 %0, t; }" : "=r"(a) : "l"(p));
    return a;
}
__device__ __forceinline__ void ldsm4(uint32_t* r, uint32_t addr) {
    asm volatile("ldmatrix.sync.aligned.m8n8.x4.shared.b16 {%0,%1,%2,%3}, [%4];"
                 : "=r"(r[0]), "=r"(r[1]), "=r"(r[2]), "=r"(r[3]) : "r"(addr));
}
__device__ __forceinline__ void mma16(float* d, const uint32_t* a, uint32_t b0, uint32_t b1) {
    asm volatile("mma.sync.aligned.m16n8k16.row.col.f32.f16.f16.f32 "
                 "{%0,%1,%2,%3}, {%4,%5,%6,%7}, {%8,%9}, {%0,%1,%2,%3};"
                 : "+f"(d[0]), "+f"(d[1]), "+f"(d[2]), "+f"(d[3])
                 : "r"(a[0]), "r"(a[1]), "r"(a[2]), "r"(a[3]), "r"(b0), "r"(b1));
}
__device__ __forceinline__ void cp16(uint32_t dst, const void* src) {
    asm volatile("cp.async.cg.shared.global [%0], [%1], 16;"
                 :: "r"(dst), "l"(__cvta_generic_to_global(src)) : "memory");
}
#define CP_COMMIT() asm volatile("cp.async.commit_group;" ::: "memory")
#define CP_WAIT(n)  asm volatile("cp.async.wait_group %0;" :: "n"(n) : "memory")

// Repacked fp16 weights: [tap][f][c], tap = th*3+tw  (8KB per tap, contiguous)
__device__ __half g_w3[9 * FF * CIN];

__global__ void wre3_kernel(const float* __restrict__ kin) {
    int idx = blockIdx.x * blockDim.x + threadIdx.x;
    if (idx >= 9 * FF * CIN) return;
    int c   = idx & 63;
    int f   = (idx >> 6) & 63;
    int tap = idx >> 12;
    int th = tap / 3, tw = tap % 3;
    g_w3[idx] = __float2half_rn(kin[((f * CIN + c) * 3 + th) * 3 + tw]);
}

struct Ctx {
    uint32_t sb;
    uint32_t rbB0, rbB1;
    int r, jb, mA, kcA, sB, kcB;
};

// One k16 round: it = tap*4 + ks
__device__ __forceinline__ void round_it(const Ctx& cx, int it, float (&acc)[2][4][4]) {
    const int tap = it >> 2, ks = it & 3;
    const int th = tap / 3, tw = tap - 3 * th;
    const int rowA0 = (cx.r + 2 - th) * SROWSH + (cx.jb + 2 - tw) + cx.mA;
    const uint32_t rbA0 = cx.sb + (uint32_t)(rowA0 * 128);
    const int sA = rowA0 & 7;
    const uint32_t wt = (uint32_t)(tap * 8192);
    const int ca = 2 * ks + cx.kcA;
    const int cb = 2 * ks + cx.kcB;

    uint32_t a0[4], a1[4], b0[4], b1[4];
    ldsm4(a0, rbA0 + ((ca ^ sA) << 4));
    ldsm4(a1, rbA0 + 16 * 128 + ((ca ^ sA) << 4));
    ldsm4(b0, cx.rbB0 + wt + ((cb ^ cx.sB) << 4));
    ldsm4(b1, cx.rbB1 + wt + ((cb ^ cx.sB) << 4));

    mma16(acc[0][0], a0, b0[0], b0[2]); mma16(acc[1][0], a1, b0[0], b0[2]);
    mma16(acc[0][1], a0, b0[1], b0[3]); mma16(acc[1][1], a1, b0[1], b0[3]);
    mma16(acc[0][2], a0, b1[0], b1[2]); mma16(acc[1][2], a1, b1[0], b1[2]);
    mma16(acc[0][3], a0, b1[1], b1[3]); mma16(acc[1][3], a1, b1[1], b1[3]);
}

__global__ __launch_bounds__(256, 2)
void conv_mma(const float* __restrict__ x,
              const float* __restrict__ bias,
              float* __restrict__ out) {
    extern __shared__ char smc[];
    const uint32_t sb    = smem_u32(smc);
    const uint32_t sb_ws = sb + WS_BYTE_OFF;
    float* sbias = (float*)(smc + BIAS_BYTE_OFF);

    const int tid = threadIdx.x;
    const int b  = blockIdx.x >> 5;
    const int i0 = (blockIdx.x & 31) * 2;       // 2 output rows per CTA

    // ---- weight staging, group A: taps 0-4 (2560 x 16B chunks) ----
    #pragma unroll
    for (int k = 0; k < 10; ++k) {
        int ch = tid + 256 * k;                 // 0..2559
        int fr = ch >> 3;
        int k8 = ch & 7;
        cp16(sb_ws + (uint32_t)(fr * 128 + ((k8 ^ (fr & 7)) << 4)),
             g_w3 + fr * 64 + k8 * 8);
    }
    CP_COMMIT();
    // ---- group B: taps 5-8 (2048 chunks) ----
    #pragma unroll
    for (int k = 0; k < 8; ++k) {
        int ch = 2560 + tid + 256 * k;          // 2560..4607
        int fr = ch >> 3;
        int k8 = ch & 7;
        cp16(sb_ws + (uint32_t)(fr * 128 + ((k8 ^ (fr & 7)) << 4)),
             g_w3 + fr * 64 + k8 * 8);
    }
    CP_COMMIT();

    // ---- x LDGs first (hide DRAM latency under zero-fill/STS below) ----
    const int c4 = tid & 15;
    const int jh = tid >> 4;
    const int sub = (c4 & 1) * 8;
    float4 vx[4][4];
    #pragma unroll
    for (int t = 0; t < 4; ++t) {
        int row = i0 - 3 + t;
        if (row < 0) continue;
        const float4* src = (const float4*)(x + ((size_t)(b * HH + row) * WW) * CIN);
        #pragma unroll
        for (int jj = 0; jj < 4; ++jj)
            vx[t][jj] = src[(jj * 16 + jh) * (CIN / 4) + c4];
    }

    // ---- zero padding rows ----
    {
        uint4 z = make_uint4(0u, 0u, 0u, 0u);
        if (tid < 96) {
            int t = tid / 24, q = tid % 24;
            *(uint4*)(smc + t * (SROWSH * 128) + q * 16) = z;
        }
        int nneg = (i0 == 0) ? 3 : (i0 == 2 ? 1 : 0);
        if (nneg) {
            uint4* p = (uint4*)smc;
            for (int k = tid; k < nneg * SROWSH * 8; k += 256) p[k] = z;
        }
    }

    // ---- convert + store staged x (pixel-major fp16, swizzled) ----
    #pragma unroll
    for (int t = 0; t < 4; ++t) {
        int row = i0 - 3 + t;
        if (row < 0) continue;
        #pragma unroll
        for (int jj = 0; jj < 4; ++jj) {
            float4 v = vx[t][jj];
            __half2 h0 = __float22half2_rn(make_float2(v.x, v.y));
            __half2 h1 = __float22half2_rn(make_float2(v.z, v.w));
            uint2 w;
            w.x = *(uint32_t*)&h0;
            w.y = *(uint32_t*)&h1;
            int rowid = t * SROWSH + (jj * 16 + jh) + 3;
            *(uint2*)(smc + rowid * 128 + (((c4 >> 1) ^ (rowid & 7)) << 4) + sub) = w;
        }
    }
    if (tid < 64) sbias[tid] = bias[tid];

    // ---- warp tiling: 8 warps = 4 m-groups (32 px) x 2 n-groups (32 filters) ----
    const int lane = tid & 31, wid = tid >> 5;
    const int lq = lane >> 2, lr = lane & 3;
    const int wm = wid >> 1;

    Ctx cx;
    cx.sb  = sb;
    cx.r   = wm >> 1;
    cx.jb  = (wm & 1) * 32;
    cx.mA  = lane & 15;
    cx.kcA = lane >> 4;
    cx.kcB = lane >> 4;
    const int n0 = (wid & 1) * 32;
    const int fB = (lane & 7) + 8 * ((lane >> 3) & 1);
    cx.sB   = fB & 7;
    cx.rbB0 = sb_ws + (uint32_t)((n0 + fB) * 128);
    cx.rbB1 = cx.rbB0 + 16 * 128;

    float acc[2][4][4];
    #pragma unroll
    for (int mt = 0; mt < 2; ++mt)
        #pragma unroll
        for (int nt = 0; nt < 4; ++nt)
            #pragma unroll
            for (int q = 0; q < 4; ++q) acc[mt][nt][q] = 0.0f;

    // ---- phase 1: wait group A only (taps 0-4 + x staged), rounds 0..19 ----
    CP_WAIT(1);
    __syncthreads();
    #pragma unroll
    for (int it = 0; it < 20; ++it) round_it(cx, it, acc);

    // ---- phase 2: taps 5-8 arrived during phase 1 ----
    CP_WAIT(0);
    __syncthreads();
    #pragma unroll
    for (int it = 20; it < 36; ++it) round_it(cx, it, acc);

    // ---- epilogue: bias + store. acc rows = pixel lq (+8), cols = 2*lr (+1) ----
    const int i = i0 + cx.r;
    #pragma unroll
    for (int mt = 0; mt < 2; ++mt) {
        int j = cx.jb + mt * 16 + lq;
        float* o0 = out + (((size_t)(b * HH + i) * WW + j) * FF);
        float* o1 = o0 + 8 * FF;                // pixel +8
        #pragma unroll
        for (int nt = 0; nt < 4; ++nt) {
            int f = n0 + nt * 8 + 2 * lr;
            float2 v0 = make_float2(acc[mt][nt][0] + sbias[f], acc[mt][nt][1] + sbias[f + 1]);
            float2 v1 = make_float2(acc[mt][nt][2] + sbias[f], acc[mt][nt][3] + sbias[f + 1]);
            *(float2*)(o0 + f) = v0;
            *(float2*)(o1 + f) = v1;
        }
    }
}

extern "C" void kernel_launch(void* const* d_in, const int* in_sizes, int n_in,
                              void* d_out, int out_size) {
    const float* x    = (const float*)d_in[0];
    const float* kern = (const float*)d_in[1];
    const float* bias = (const float*)d_in[2];
    float* out = (float*)d_out;

    cudaFuncSetAttribute(conv_mma, cudaFuncAttributeMaxDynamicSharedMemorySize, SMEM_BYTES);

    wre3_kernel<<<(9 * FF * CIN + 255) / 256, 256>>>(kern);
    conv_mma<<<BATCH * 32, 256, SMEM_BYTES>>>(x, bias, out);
}